// round 16
// baseline (speedup 1.0000x reference)
#include <cuda_runtime.h>
#include <cuda_fp16.h>
#include <cstdint>

typedef unsigned int u32;
typedef unsigned long long u64;

#define NMAX 100000

// ---------------- persistent scratch ----------------
__device__ float g_nf[NMAX * 128];
__device__ __align__(16) __half g_w1h[256 * 128];    // BN-folded, fp16 RN
__device__ __align__(16) __half g_w2h[256 * 256];
__device__ __align__(16) __half g_nw1h[128 * 128];   // BN-folded
__device__ __align__(16) __half g_nw2h[128 * 128];
__device__ float g_b1f[256];
__device__ float g_nb1f[128];

// ---------------- helpers ----------------
__device__ __forceinline__ u32 s2u(const void* p) {
    u32 a;
    asm("{ .reg .u64 t; cvta.to.shared.u64 t, %1; cvt.u32.u64 %0, t; }" : "=r"(a) : "l"(p));
    return a;
}
__device__ __forceinline__ void ldsm4(u32 a, u32& r0, u32& r1, u32& r2, u32& r3) {
    asm volatile("ldmatrix.sync.aligned.m8n8.x4.shared.b16 {%0,%1,%2,%3}, [%4];"
                 : "=r"(r0), "=r"(r1), "=r"(r2), "=r"(r3) : "r"(a));
}
__device__ __forceinline__ void sts32(u32 a, u32 v) {
    asm volatile("st.shared.b32 [%0], %1;" :: "r"(a), "r"(v));
}
__device__ __forceinline__ void sts64(u32 a, u32 x, u32 y) {
    asm volatile("st.shared.v2.b32 [%0], {%1,%2};" :: "r"(a), "r"(x), "r"(y));
}
__device__ __forceinline__ void cpa16(u32 dst, const void* src) {
    asm volatile("cp.async.cg.shared.global [%0], [%1], 16;" :: "r"(dst), "l"(src));
}
#define CP_COMMIT() asm volatile("cp.async.commit_group;")
#define CP_WAIT0()  asm volatile("cp.async.wait_group 0;")

__device__ __forceinline__ void mma16816(float* d, const u32* a, u32 b0, u32 b1) {
    asm volatile(
        "mma.sync.aligned.m16n8k16.row.col.f32.f16.f16.f32 "
        "{%0,%1,%2,%3}, {%4,%5,%6,%7}, {%8,%9}, {%0,%1,%2,%3};"
        : "+f"(d[0]), "+f"(d[1]), "+f"(d[2]), "+f"(d[3])
        : "r"(a[0]), "r"(a[1]), "r"(a[2]), "r"(a[3]), "r"(b0), "r"(b1));
}
__device__ __forceinline__ void red4(float* p, float a, float b, float c, float d) {
    asm volatile("red.global.add.v4.f32 [%0], {%1,%2,%3,%4};"
                 :: "l"(p), "f"(a), "f"(b), "f"(c), "f"(d) : "memory");
}
__device__ __forceinline__ u32 pack2h(__half a, __half b) {
    return (u32)__half_as_ushort(a) | ((u32)__half_as_ushort(b) << 16);
}

// ---------------- prep ----------------
__global__ void k_zero(int n4) {
    int i = blockIdx.x * blockDim.x + threadIdx.x;
    if (i < n4) reinterpret_cast<float4*>(g_nf)[i] = make_float4(0.f, 0.f, 0.f, 0.f);
}
// blocks [0,512): weight convert; blocks [512,560): bias folding
__global__ void k_prep(const float* __restrict__ W1, const float* __restrict__ og,
                       const float* __restrict__ ov, const float* __restrict__ W2,
                       const float* __restrict__ NW1, const float* __restrict__ ng,
                       const float* __restrict__ nv, const float* __restrict__ NW2,
                       const float* __restrict__ ob1, const float* __restrict__ ob,
                       const float* __restrict__ om, const float* __restrict__ nb1,
                       const float* __restrict__ nb, const float* __restrict__ nm) {
    int blk = blockIdx.x;
    if (blk < 512) {
        int i = blk * 256 + threadIdx.x;
        if (i < 32768) {
            int k = i & 127;
            g_w1h[i] = __float2half_rn(W1[i] * (og[k] * rsqrtf(ov[k] + 1e-5f)));
        } else if (i < 98304) {
            int j = i - 32768;
            g_w2h[j] = __float2half_rn(W2[j]);
        } else if (i < 114688) {
            int j = i - 98304;
            int k = j & 127;
            g_nw1h[j] = __float2half_rn(NW1[j] * (ng[k] * rsqrtf(nv[k] + 1e-5f)));
        } else {
            int j = i - 114688;
            g_nw2h[j] = __float2half_rn(NW2[j]);
        }
    } else {
        int job = (blk - 512) * 8 + (threadIdx.x >> 5);
        int lane = threadIdx.x & 31;
        if (job < 256) {
            float s = 0.f;
            for (int k = lane; k < 128; k += 32) {
                float sc = og[k] * rsqrtf(ov[k] + 1e-5f);
                s += W1[job * 128 + k] * (ob[k] - om[k] * sc);
            }
            for (int o = 16; o; o >>= 1) s += __shfl_xor_sync(~0u, s, o);
            if (lane == 0) g_b1f[job] = ob1[job] + s;
        } else if (job < 384) {
            int n = job - 256;
            float s = 0.f;
            for (int k = lane; k < 128; k += 32) {
                float sc = ng[k] * rsqrtf(nv[k] + 1e-5f);
                s += NW1[n * 128 + k] * (nb[k] - nm[k] * sc);
            }
            for (int o = 16; o; o >>= 1) s += __shfl_xor_sync(~0u, s, o);
            if (lane == 0) g_nb1f[n] = nb1[n] + s;
        }
    }
}

// ---------------------------------------------------------------------------
// Kernel 1: PERSISTENT MLP1 + scatter. 64 tokens/tile, 256 threads, 2 CTAs/SM,
// warp tile 32x64, pure fp16 1-term GEMMs.
// Aliasing discipline (W1H 16K..80K overlaps BUF0 32K..64K and BUF1 64K..96K):
//   - W1 is issued ONLY while both BUFs are dead (loop top, after convert).
//   - W2 slab0+slab1 are issued ONLY after GEMM1 (W1H dead), with epilogue
//     covering their latency.
// Pipeline: next-x staged into BUF0 during GEMM2 slab3; scatter of tile i
// overlaps W1 load of tile i+1.
// ---------------------------------------------------------------------------
#define K1_XAH   0u
#define K1_W1H   16384u
#define K1_A2H   0u
#define K1_BUF0  32768u
#define K1_BUF1  65536u
#define K1_B1    98304u
#define K1_B2    99328u
#define K1_SMEM  100352u

__global__ void __launch_bounds__(256, 2) k_mlp1(
    const float* __restrict__ x, const int* __restrict__ tok,
    const float* __restrict__ b2g, int T, int ntiles)
{
    extern __shared__ char sm[];
    const u32 sb = s2u(sm);
    const int tid = threadIdx.x, wid = tid >> 5, l = tid & 31;
    const int lr8 = l & 7;
    const int g = l >> 2, q = l & 3;
    const int wm = (wid & 1) * 32, wn = (wid >> 1) * 64;
    const u32 keyX = (u32)lr8 << 4;
    const u32 aCX = (u32)((l >> 4) & 1) * 16;
    const u32 bCX = (u32)((l >> 3) & 1) * 16;
    const int cofs = (wn < 128) ? 0 : 128;
    const bool evenq = ((q & 1) == 0);

    ((float*)(sm + K1_B1))[tid] = g_b1f[tid];
    ((float*)(sm + K1_B2))[tid] = b2g[tid];

    float acc[2][8][4];
    int pt0 = -1;

    // prologue: stage first tile's x (fp32 row-major 64x512B) into BUF0
    int tile = blockIdx.x;
    if (tile < ntiles) {
        int t0 = tile * 64;
        #pragma unroll
        for (int i = 0; i < 8; ++i) {
            int idx = tid + i * 256;                 // 16B chunk 0..2047
            int r = idx >> 5, ch = idx & 31;
            if (t0 + r < T)
                cpa16(sb + K1_BUF0 + (u32)idx * 16,
                      (const char*)(x + (size_t)(t0 + r) * 128) + ch * 16);
        }
    }
    CP_COMMIT();

    #pragma unroll 1
    for (; tile < ntiles; tile += gridDim.x) {
        const int t0 = tile * 64;

        CP_WAIT0();
        __syncthreads();                             // staged x visible CTA-wide

        // convert staged fp32 (BUF0) -> fp16 XAH
        #pragma unroll
        for (int i = 0; i < 8; ++i) {
            int idx = tid + i * 256;
            int r = idx >> 5, c = (idx & 31) * 4;
            float4 v = *reinterpret_cast<const float4*>(sm + K1_BUF0 + (u32)idx * 16);
            u32 h01 = pack2h(__float2half_rn(v.x), __float2half_rn(v.y));
            u32 h23 = pack2h(__float2half_rn(v.z), __float2half_rn(v.w));
            u32 o = (u32)r * 256 + (((u32)c * 2) ^ (((u32)(r & 7)) << 4));
            sts64(sb + K1_XAH + o, h01, h23);
        }
        __syncthreads();                             // XAH ready; BUF0/BUF1 dead

        // issue W1 only (64K; overlaps dead BUF regions — safe)
        #pragma unroll
        for (int i = 0; i < 16; ++i) {
            int idx = tid + i * 256;                 // 0..4095
            int n = idx >> 4, seg = idx & 15;
            u32 o = (u32)n * 256 + (u32)seg * 16;
            cpa16(sb + K1_W1H + (o ^ (((u32)(n & 7)) << 4)), (const char*)g_w1h + o);
        }
        CP_COMMIT();

        // scatter PREVIOUS tile (overlaps the W1 load above)
        if (pt0 >= 0) {
            const float* b2s = (const float*)(sm + K1_B2);
            #pragma unroll
            for (int mt = 0; mt < 2; ++mt) {
                int tA = pt0 + wm + mt * 16 + g;
                int tB = tA + 8;
                float* rowA = nullptr; float* rowB = nullptr;
                if (tA < T) {
                    int nd = (cofs == 0) ? tok[tA] : tok[T + tA];
                    rowA = g_nf + (size_t)nd * 128;
                }
                if (tB < T) {
                    int nd = (cofs == 0) ? tok[tB] : tok[T + tB];
                    rowB = g_nf + (size_t)nd * 128;
                }
                #pragma unroll
                for (int nt = 0; nt < 8; ++nt) {
                    int c0 = wn + nt * 8 + q * 2;
                    float bx = b2s[c0], by = b2s[c0 + 1];
                    float a0 = acc[mt][nt][0] + bx;
                    float a1 = acc[mt][nt][1] + by;
                    float a2 = acc[mt][nt][2] + bx;
                    float a3 = acc[mt][nt][3] + by;
                    float p0 = __shfl_xor_sync(0xffffffffu, a0, 1);
                    float p1 = __shfl_xor_sync(0xffffffffu, a1, 1);
                    float p2 = __shfl_xor_sync(0xffffffffu, a2, 1);
                    float p3 = __shfl_xor_sync(0xffffffffu, a3, 1);
                    if (evenq) {
                        int cl = c0 - cofs;
                        if (rowA) red4(rowA + cl, a0, a1, p0, p1);
                        if (rowB) red4(rowB + cl, a2, a3, p2, p3);
                    }
                }
            }
        }
        pt0 = t0;

        CP_WAIT0();
        __syncthreads();                             // W1 ready

        // ---------------- GEMM1: y1 = x @ W1^T ----------------
        #pragma unroll
        for (int mt = 0; mt < 2; ++mt)
            #pragma unroll
            for (int nt = 0; nt < 8; ++nt)
                #pragma unroll
                for (int j = 0; j < 4; ++j) acc[mt][nt][j] = 0.f;
        {
            const u32 PA = K1_XAH + (u32)(wm + lr8 + ((l >> 3) & 1) * 8) * 256u + keyX;
            const u32 PB = K1_W1H + (u32)(wn + lr8 + ((l >> 4) & 1) * 8) * 256u + keyX;
            #pragma unroll
            for (int kt = 0; kt < 8; ++kt) {
                u32 ca = (u32)kt * 32 + aCX, cb = (u32)kt * 32 + bCX;
                u32 Ah[2][4];
                ldsm4(sb + ((PA)         ^ ca), Ah[0][0], Ah[0][1], Ah[0][2], Ah[0][3]);
                ldsm4(sb + ((PA + 4096u) ^ ca), Ah[1][0], Ah[1][1], Ah[1][2], Ah[1][3]);
                #pragma unroll
                for (int ntg = 0; ntg < 4; ++ntg) {
                    u32 bh[4];
                    ldsm4(sb + ((PB + (u32)ntg * 4096u) ^ cb), bh[0], bh[1], bh[2], bh[3]);
                    #pragma unroll
                    for (int sub = 0; sub < 2; ++sub) {
                        int nt = ntg * 2 + sub;
                        #pragma unroll
                        for (int mt = 0; mt < 2; ++mt)
                            mma16816(acc[mt][nt], Ah[mt], bh[sub * 2], bh[sub * 2 + 1]);
                    }
                }
            }
        }
        __syncthreads();                             // XAH/W1H reads done

        // issue W2 slab0 -> BUF0 and slab1 -> BUF1 (W1H dead now; epilogue
        // below covers the load latency)
        #pragma unroll
        for (int i = 0; i < 8; ++i) {
            int idx = tid + i * 256;                 // 0..2047
            int n = idx >> 3, seg = idx & 7;
            u32 o = (u32)n * 128 + (u32)seg * 16;
            u32 sw = o ^ (((u32)(n & 7)) << 4);
            cpa16(sb + K1_BUF0 + sw,
                  (const char*)g_w2h + (size_t)n * 512 + (size_t)seg * 16);
            cpa16(sb + K1_BUF1 + sw,
                  (const char*)g_w2h + (size_t)n * 512 + 128 + (size_t)seg * 16);
        }
        CP_COMMIT();

        // epilogue1: A2 = fp16(relu(y1 + b1f)), 64 rows x 512B
        {
            const float* b1s = (const float*)(sm + K1_B1);
            const u32 kr = (u32)g << 4;
            #pragma unroll
            for (int mt = 0; mt < 2; ++mt) {
                u32 row = (u32)(wm + mt * 16 + g);
                #pragma unroll
                for (int nt = 0; nt < 8; ++nt) {
                    int c0 = wn + nt * 8 + q * 2;
                    float bx = b1s[c0], by = b1s[c0 + 1];
                    float f0 = fmaxf(acc[mt][nt][0] + bx, 0.f);
                    float f1 = fmaxf(acc[mt][nt][1] + by, 0.f);
                    float f2 = fmaxf(acc[mt][nt][2] + bx, 0.f);
                    float f3 = fmaxf(acc[mt][nt][3] + by, 0.f);
                    u32 col = ((u32)c0 * 2) ^ kr;
                    sts32(sb + K1_A2H + row * 512 + col,
                          pack2h(__float2half_rn(f0), __float2half_rn(f1)));
                    sts32(sb + K1_A2H + (row + 8) * 512 + col,
                          pack2h(__float2half_rn(f2), __float2half_rn(f3)));
                }
            }
        }
        CP_WAIT0();
        __syncthreads();                             // A2 + slabs 0,1 ready

        // ---------------- GEMM2: y2 = A2 @ W2^T (4 slabs of k=64) ----------
        #pragma unroll
        for (int mt = 0; mt < 2; ++mt)
            #pragma unroll
            for (int nt = 0; nt < 8; ++nt)
                #pragma unroll
                for (int j = 0; j < 4; ++j) acc[mt][nt][j] = 0.f;
        {
            const u32 PA2 = K1_A2H + (u32)(wm + lr8 + ((l >> 3) & 1) * 8) * 512u + keyX;
            const u32 PW2 = ((u32)(wn + lr8 + ((l >> 4) & 1) * 8) * 128u) ^ keyX;
            #pragma unroll 1
            for (int s = 0; s < 4; ++s) {
                if (s == 1 || s == 2) {
                    // prefetch slab s+1 into the buffer freed by slab s-1
                    u32 dB = (s == 1) ? K1_BUF0 : K1_BUF1;
                    #pragma unroll
                    for (int i = 0; i < 8; ++i) {
                        int idx = tid + i * 256;
                        int n = idx >> 3, seg = idx & 7;
                        u32 o = (u32)n * 128 + (u32)seg * 16;
                        size_t src = (size_t)n * 512 + (size_t)(s + 1) * 128 + (size_t)seg * 16;
                        cpa16(sb + dB + (o ^ (((u32)(n & 7)) << 4)), (const char*)g_w2h + src);
                    }
                    CP_COMMIT();
                } else if (s == 3) {
                    // stage NEXT tile's x into BUF0 (freed after slab2)
                    int tile2 = tile + gridDim.x;
                    if (tile2 < ntiles) {
                        int nt0 = tile2 * 64;
                        #pragma unroll
                        for (int i = 0; i < 8; ++i) {
                            int idx = tid + i * 256;
                            int r = idx >> 5, ch = idx & 31;
                            if (nt0 + r < T)
                                cpa16(sb + K1_BUF0 + (u32)idx * 16,
                                      (const char*)(x + (size_t)(nt0 + r) * 128) + ch * 16);
                        }
                    }
                    CP_COMMIT();
                }
                u32 bB = sb + ((s & 1) ? K1_BUF1 : K1_BUF0);
                #pragma unroll
                for (int ktL = 0; ktL < 4; ++ktL) {
                    int kt = s * 4 + ktL;
                    u32 ca = (u32)kt * 32 + aCX;
                    u32 cw = (u32)ktL * 32 + bCX;
                    u32 Ah[2][4];
                    ldsm4(sb + ((PA2)         ^ ca), Ah[0][0], Ah[0][1], Ah[0][2], Ah[0][3]);
                    ldsm4(sb + ((PA2 + 8192u) ^ ca), Ah[1][0], Ah[1][1], Ah[1][2], Ah[1][3]);
                    #pragma unroll
                    for (int ntg = 0; ntg < 4; ++ntg) {
                        u32 bh[4];
                        ldsm4(bB + ((PW2 + (u32)ntg * 2048u) ^ cw), bh[0], bh[1], bh[2], bh[3]);
                        #pragma unroll
                        for (int sub = 0; sub < 2; ++sub) {
                            int nt = ntg * 2 + sub;
                            #pragma unroll
                            for (int mt = 0; mt < 2; ++mt)
                                mma16816(acc[mt][nt], Ah[mt], bh[sub * 2], bh[sub * 2 + 1]);
                        }
                    }
                }
                if (s < 3) { CP_WAIT0(); }
                __syncthreads();
            }
        }
        // next-x wait at loop top; acc carries to next iteration's scatter
    }

    // final scatter
    if (pt0 >= 0) {
        const float* b2s = (const float*)(sm + K1_B2);
        #pragma unroll
        for (int mt = 0; mt < 2; ++mt) {
            int tA = pt0 + wm + mt * 16 + g;
            int tB = tA + 8;
            float* rowA = nullptr; float* rowB = nullptr;
            if (tA < T) {
                int nd = (cofs == 0) ? tok[tA] : tok[T + tA];
                rowA = g_nf + (size_t)nd * 128;
            }
            if (tB < T) {
                int nd = (cofs == 0) ? tok[tB] : tok[T + tB];
                rowB = g_nf + (size_t)nd * 128;
            }
            #pragma unroll
            for (int nt = 0; nt < 8; ++nt) {
                int c0 = wn + nt * 8 + q * 2;
                float bx = b2s[c0], by = b2s[c0 + 1];
                float a0 = acc[mt][nt][0] + bx;
                float a1 = acc[mt][nt][1] + by;
                float a2 = acc[mt][nt][2] + bx;
                float a3 = acc[mt][nt][3] + by;
                float p0 = __shfl_xor_sync(0xffffffffu, a0, 1);
                float p1 = __shfl_xor_sync(0xffffffffu, a1, 1);
                float p2 = __shfl_xor_sync(0xffffffffu, a2, 1);
                float p3 = __shfl_xor_sync(0xffffffffu, a3, 1);
                if (evenq) {
                    int cl = c0 - cofs;
                    if (rowA) red4(rowA + cl, a0, a1, p0, p1);
                    if (rowB) red4(rowB + cl, a2, a3, p2, p3);
                }
            }
        }
    }
}

// ---------------------------------------------------------------------------
// Kernel 2: MLP2. 64 nodes/CTA, 256 threads (8 warps, 2x4), warp tile 32x32.
// Pure fp16 1-term GEMMs. XAH 0(16K) WH 16K(32K). Unchanged (known-good).
// ---------------------------------------------------------------------------
#define K2_XAH  0u
#define K2_WH   16384u
#define K2_B1   49152u
#define K2_B2   49664u
#define K2_SMEM 50176u

__global__ void __launch_bounds__(256, 2) k_mlp2(
    const float* __restrict__ b2g, float* __restrict__ out, int NN)
{
    extern __shared__ char sm[];
    const u32 sb = s2u(sm);
    const int tid = threadIdx.x, wid = tid >> 5, l = tid & 31;
    const int lr8 = l & 7;
    const int g = l >> 2, q = l & 3;
    const int wm = (wid & 1) * 32, wn = (wid >> 1) * 32;
    const int n0 = blockIdx.x * 64;
    const u32 keyX = (u32)lr8 << 4;
    const u32 aCX = (u32)((l >> 4) & 1) * 16;
    const u32 bCX = (u32)((l >> 3) & 1) * 16;

    if (tid < 128) {
        ((float*)(sm + K2_B1))[tid] = g_nb1f[tid];
        ((float*)(sm + K2_B2))[tid] = b2g[tid];
    }

    // W1' resident (128 rows x 256B = 32K)
    #pragma unroll
    for (int i = 0; i < 8; ++i) {
        int idx = tid + i * 256;                      // 0..2047
        int n = idx >> 4, seg = idx & 15;
        u32 o = (u32)n * 256 + (u32)seg * 16;
        cpa16(sb + K2_WH + (o ^ (((u32)(n & 7)) << 4)), (const char*)g_nw1h + o);
    }
    CP_COMMIT();

    // nf tile [64,128] -> fp16 (hi only)
    #pragma unroll
    for (int i = 0; i < 8; ++i) {
        int idx = tid + i * 256;
        int r = idx >> 5, c = (idx & 31) * 4;
        float4 v = make_float4(0.f, 0.f, 0.f, 0.f);
        if (n0 + r < NN) v = *reinterpret_cast<const float4*>(g_nf + (size_t)(n0 + r) * 128 + c);
        u32 h01 = pack2h(__float2half_rn(v.x), __float2half_rn(v.y));
        u32 h23 = pack2h(__float2half_rn(v.z), __float2half_rn(v.w));
        u32 o = (u32)r * 256 + (((u32)c * 2) ^ (((u32)(r & 7)) << 4));
        sts64(sb + K2_XAH + o, h01, h23);
    }
    CP_WAIT0();
    __syncthreads();

    float acc[2][4][4];
    const u32 PA = K2_XAH + (u32)(wm + lr8 + ((l >> 3) & 1) * 8) * 256u + keyX;
    const u32 PB = K2_WH  + (u32)(wn + lr8 + ((l >> 4) & 1) * 8) * 256u + keyX;

    // ---- GEMM1 (1-term) ----
    #pragma unroll
    for (int mt = 0; mt < 2; ++mt)
        #pragma unroll
        for (int nt = 0; nt < 4; ++nt)
            #pragma unroll
            for (int j = 0; j < 4; ++j) acc[mt][nt][j] = 0.f;

    #pragma unroll
    for (int kt = 0; kt < 8; ++kt) {
        u32 ca = (u32)kt * 32 + aCX, cb = (u32)kt * 32 + bCX;
        u32 Ah[2][4];
        ldsm4(sb + ((PA)         ^ ca), Ah[0][0], Ah[0][1], Ah[0][2], Ah[0][3]);
        ldsm4(sb + ((PA + 4096u) ^ ca), Ah[1][0], Ah[1][1], Ah[1][2], Ah[1][3]);
        #pragma unroll
        for (int ntg = 0; ntg < 2; ++ntg) {
            u32 bh[4];
            ldsm4(sb + ((PB + (u32)ntg * 4096u) ^ cb), bh[0], bh[1], bh[2], bh[3]);
            #pragma unroll
            for (int sub = 0; sub < 2; ++sub) {
                int nt = ntg * 2 + sub;
                #pragma unroll
                for (int mt = 0; mt < 2; ++mt)
                    mma16816(acc[mt][nt], Ah[mt], bh[sub * 2], bh[sub * 2 + 1]);
            }
        }
    }
    __syncthreads();

    // prefetch W2' over WH
    #pragma unroll
    for (int i = 0; i < 8; ++i) {
        int idx = tid + i * 256;
        int n = idx >> 4, seg = idx & 15;
        u32 o = (u32)n * 256 + (u32)seg * 16;
        cpa16(sb + K2_WH + (o ^ (((u32)(n & 7)) << 4)), (const char*)g_nw2h + o);
    }
    CP_COMMIT();

    // epilogue1 -> A2 over XA (stride 256B, hi only)
    {
        const float* b1s = (const float*)(sm + K2_B1);
        const u32 kr = (u32)g << 4;
        #pragma unroll
        for (int mt = 0; mt < 2; ++mt) {
            u32 row = (u32)(wm + mt * 16 + g);
            #pragma unroll
            for (int nt = 0; nt < 4; ++nt) {
                int c0 = wn + nt * 8 + q * 2;
                float bx = b1s[c0], by = b1s[c0 + 1];
                float f0 = fmaxf(acc[mt][nt][0] + bx, 0.f);
                float f1 = fmaxf(acc[mt][nt][1] + by, 0.f);
                float f2 = fmaxf(acc[mt][nt][2] + bx, 0.f);
                float f3 = fmaxf(acc[mt][nt][3] + by, 0.f);
                u32 col = ((u32)c0 * 2) ^ kr;
                sts32(sb + K2_XAH + row * 256 + col,
                      pack2h(__float2half_rn(f0), __float2half_rn(f1)));
                sts32(sb + K2_XAH + (row + 8) * 256 + col,
                      pack2h(__float2half_rn(f2), __float2half_rn(f3)));
            }
        }
    }
    CP_WAIT0();
    __syncthreads();

    // ---- GEMM2 (1-term) ----
    #pragma unroll
    for (int mt = 0; mt < 2; ++mt)
        #pragma unroll
        for (int nt = 0; nt < 4; ++nt)
            #pragma unroll
            for (int j = 0; j < 4; ++j) acc[mt][nt][j] = 0.f;

    #pragma unroll
    for (int kt = 0; kt < 8; ++kt) {
        u32 ca = (u32)kt * 32 + aCX, cb = (u32)kt * 32 + bCX;
        u32 Ah[2][4];
        ldsm4(sb + ((PA)         ^ ca), Ah[0][0], Ah[0][1], Ah[0][2], Ah[0][3]);
        ldsm4(sb + ((PA + 4096u) ^ ca), Ah[1][0], Ah[1][1], Ah[1][2], Ah[1][3]);
        #pragma unroll
        for (int ntg = 0; ntg < 2; ++ntg) {
            u32 bh[4];
            ldsm4(sb + ((PB + (u32)ntg * 4096u) ^ cb), bh[0], bh[1], bh[2], bh[3]);
            #pragma unroll
            for (int sub = 0; sub < 2; ++sub) {
                int nt = ntg * 2 + sub;
                #pragma unroll
                for (int mt = 0; mt < 2; ++mt)
                    mma16816(acc[mt][nt], Ah[mt], bh[sub * 2], bh[sub * 2 + 1]);
            }
        }
    }

    // output
    {
        const float* b2s = (const float*)(sm + K2_B2);
        #pragma unroll
        for (int mt = 0; mt < 2; ++mt) {
            int rA = n0 + wm + mt * 16 + g;
            int rB = rA + 8;
            #pragma unroll
            for (int nt = 0; nt < 4; ++nt) {
                int c0 = wn + nt * 8 + q * 2;
                float bx = b2s[c0], by = b2s[c0 + 1];
                if (rA < NN)
                    *reinterpret_cast<float2*>(out + (size_t)rA * 128 + c0) =
                        make_float2(acc[mt][nt][0] + bx, acc[mt][nt][1] + by);
                if (rB < NN)
                    *reinterpret_cast<float2*>(out + (size_t)rB * 128 + c0) =
                        make_float2(acc[mt][nt][2] + bx, acc[mt][nt][3] + by);
            }
        }
    }
}

// ---------------------------------------------------------------------------
extern "C" void kernel_launch(void* const* d_in, const int* in_sizes, int n_in,
                              void* d_out, int out_size) {
    const float* x    = (const float*)d_in[0];
    const int*   tok  = (const int*)d_in[3];   // int32 (JAX x64 disabled)
    const float* op_g  = (const float*)d_in[4];
    const float* op_b  = (const float*)d_in[5];
    const float* op_m  = (const float*)d_in[6];
    const float* op_v  = (const float*)d_in[7];
    const float* op_w1 = (const float*)d_in[8];
    const float* op_b1 = (const float*)d_in[9];
    const float* op_w2 = (const float*)d_in[10];
    const float* op_b2 = (const float*)d_in[11];
    const float* nm_g  = (const float*)d_in[12];
    const float* nm_b  = (const float*)d_in[13];
    const float* nm_m  = (const float*)d_in[14];
    const float* nm_v  = (const float*)d_in[15];
    const float* nm_w1 = (const float*)d_in[16];
    const float* nm_b1 = (const float*)d_in[17];
    const float* nm_w2 = (const float*)d_in[18];
    const float* nm_b2 = (const float*)d_in[19];

    int T  = in_sizes[0] / 128;
    int NN = in_sizes[2];
    float* out = (float*)d_out;

    cudaFuncSetAttribute(k_mlp1, cudaFuncAttributeMaxDynamicSharedMemorySize, K1_SMEM);
    cudaFuncSetAttribute(k_mlp2, cudaFuncAttributeMaxDynamicSharedMemorySize, K2_SMEM);

    int nsm = 148;
    cudaDeviceGetAttribute(&nsm, cudaDevAttrMultiProcessorCount, 0);

    int n4 = (NN * 128) / 4;
    k_zero<<<(n4 + 255) / 256, 256>>>(n4);

    k_prep<<<560, 256>>>(op_w1, op_g, op_v, op_w2, nm_w1, nm_g, nm_v, nm_w2,
                         op_b1, op_b, op_m, nm_b1, nm_b, nm_m);

    int ntiles = (T + 63) / 64;
    int grid1 = 2 * nsm;
    if (grid1 > ntiles) grid1 = ntiles;
    k_mlp1<<<grid1, 256, K1_SMEM>>>(x, tok, op_b2, T, ntiles);

    k_mlp2<<<(NN + 63) / 64, 256, K2_SMEM>>>(nm_b2, out, NN);
}

// round 17
// speedup vs baseline: 1.0161x; 1.0161x over previous
#include <cuda_runtime.h>
#include <cuda_fp16.h>
#include <cstdint>

typedef unsigned int u32;
typedef unsigned long long u64;

#define NMAX 100000

// ---------------- persistent scratch ----------------
__device__ float g_nf[NMAX * 128];
__device__ __align__(16) __half g_w1h[256 * 128];    // BN-folded, fp16 RN
__device__ __align__(16) __half g_w2h[256 * 256];
__device__ __align__(16) __half g_nw1h[128 * 128];   // BN-folded
__device__ __align__(16) __half g_nw2h[128 * 128];
__device__ float g_b1f[256];
__device__ float g_nb1f[128];

// ---------------- helpers ----------------
__device__ __forceinline__ u32 s2u(const void* p) {
    u32 a;
    asm("{ .reg .u64 t; cvta.to.shared.u64 t, %1; cvt.u32.u64 %0, t; }" : "=r"(a) : "l"(p));
    return a;
}
__device__ __forceinline__ void ldsm4(u32 a, u32& r0, u32& r1, u32& r2, u32& r3) {
    asm volatile("ldmatrix.sync.aligned.m8n8.x4.shared.b16 {%0,%1,%2,%3}, [%4];"
                 : "=r"(r0), "=r"(r1), "=r"(r2), "=r"(r3) : "r"(a));
}
__device__ __forceinline__ void sts32(u32 a, u32 v) {
    asm volatile("st.shared.b32 [%0], %1;" :: "r"(a), "r"(v));
}
__device__ __forceinline__ void sts64(u32 a, u32 x, u32 y) {
    asm volatile("st.shared.v2.b32 [%0], {%1,%2};" :: "r"(a), "r"(x), "r"(y));
}
__device__ __forceinline__ void cpa16(u32 dst, const void* src) {
    asm volatile("cp.async.cg.shared.global [%0], [%1], 16;" :: "r"(dst), "l"(src));
}
#define CP_COMMIT() asm volatile("cp.async.commit_group;")
#define CP_WAIT0()  asm volatile("cp.async.wait_group 0;")

__device__ __forceinline__ void mma16816(float* d, const u32* a, u32 b0, u32 b1) {
    asm volatile(
        "mma.sync.aligned.m16n8k16.row.col.f32.f16.f16.f32 "
        "{%0,%1,%2,%3}, {%4,%5,%6,%7}, {%8,%9}, {%0,%1,%2,%3};"
        : "+f"(d[0]), "+f"(d[1]), "+f"(d[2]), "+f"(d[3])
        : "r"(a[0]), "r"(a[1]), "r"(a[2]), "r"(a[3]), "r"(b0), "r"(b1));
}
__device__ __forceinline__ void red4(float* p, float a, float b, float c, float d) {
    asm volatile("red.global.add.v4.f32 [%0], {%1,%2,%3,%4};"
                 :: "l"(p), "f"(a), "f"(b), "f"(c), "f"(d) : "memory");
}
__device__ __forceinline__ u32 pack2h(__half a, __half b) {
    return (u32)__half_as_ushort(a) | ((u32)__half_as_ushort(b) << 16);
}

// ---------------- prep (weight convert + bias fold + nf zero, one kernel) ----
// blocks [0,512): weight convert; [512,560): bias folding; [560,2608): zero nf
__global__ void k_prep(const float* __restrict__ W1, const float* __restrict__ og,
                       const float* __restrict__ ov, const float* __restrict__ W2,
                       const float* __restrict__ NW1, const float* __restrict__ ng,
                       const float* __restrict__ nv, const float* __restrict__ NW2,
                       const float* __restrict__ ob1, const float* __restrict__ ob,
                       const float* __restrict__ om, const float* __restrict__ nb1,
                       const float* __restrict__ nb, const float* __restrict__ nm,
                       int n4) {
    int blk = blockIdx.x;
    if (blk < 512) {
        int i = blk * 256 + threadIdx.x;
        if (i < 32768) {
            int k = i & 127;
            g_w1h[i] = __float2half_rn(W1[i] * (og[k] * rsqrtf(ov[k] + 1e-5f)));
        } else if (i < 98304) {
            int j = i - 32768;
            g_w2h[j] = __float2half_rn(W2[j]);
        } else if (i < 114688) {
            int j = i - 98304;
            int k = j & 127;
            g_nw1h[j] = __float2half_rn(NW1[j] * (ng[k] * rsqrtf(nv[k] + 1e-5f)));
        } else {
            int j = i - 114688;
            g_nw2h[j] = __float2half_rn(NW2[j]);
        }
    } else if (blk < 560) {
        int job = (blk - 512) * 8 + (threadIdx.x >> 5);
        int lane = threadIdx.x & 31;
        if (job < 256) {
            float s = 0.f;
            for (int k = lane; k < 128; k += 32) {
                float sc = og[k] * rsqrtf(ov[k] + 1e-5f);
                s += W1[job * 128 + k] * (ob[k] - om[k] * sc);
            }
            for (int o = 16; o; o >>= 1) s += __shfl_xor_sync(~0u, s, o);
            if (lane == 0) g_b1f[job] = ob1[job] + s;
        } else if (job < 384) {
            int n = job - 256;
            float s = 0.f;
            for (int k = lane; k < 128; k += 32) {
                float sc = ng[k] * rsqrtf(nv[k] + 1e-5f);
                s += NW1[n * 128 + k] * (nb[k] - nm[k] * sc);
            }
            for (int o = 16; o; o >>= 1) s += __shfl_xor_sync(~0u, s, o);
            if (lane == 0) g_nb1f[n] = nb1[n] + s;
        }
    } else {
        int zb = blk - 560;                           // 0..2047
        for (int j = zb * 256 + threadIdx.x; j < n4; j += 2048 * 256)
            reinterpret_cast<float4*>(g_nf)[j] = make_float4(0.f, 0.f, 0.f, 0.f);
    }
}

// ---------------------------------------------------------------------------
// Kernel 1: PERSISTENT MLP1 + scatter. 64 tokens/tile, 256 threads, 2 CTAs/SM,
// warp tile 32x64, pure fp16 1-term GEMMs.  (Unchanged from passing R16.)
// ---------------------------------------------------------------------------
#define K1_XAH   0u
#define K1_W1H   16384u
#define K1_A2H   0u
#define K1_BUF0  32768u
#define K1_BUF1  65536u
#define K1_B1    98304u
#define K1_B2    99328u
#define K1_SMEM  100352u

__global__ void __launch_bounds__(256, 2) k_mlp1(
    const float* __restrict__ x, const int* __restrict__ tok,
    const float* __restrict__ b2g, int T, int ntiles)
{
    extern __shared__ char sm[];
    const u32 sb = s2u(sm);
    const int tid = threadIdx.x, wid = tid >> 5, l = tid & 31;
    const int lr8 = l & 7;
    const int g = l >> 2, q = l & 3;
    const int wm = (wid & 1) * 32, wn = (wid >> 1) * 64;
    const u32 keyX = (u32)lr8 << 4;
    const u32 aCX = (u32)((l >> 4) & 1) * 16;
    const u32 bCX = (u32)((l >> 3) & 1) * 16;
    const int cofs = (wn < 128) ? 0 : 128;
    const bool evenq = ((q & 1) == 0);

    ((float*)(sm + K1_B1))[tid] = g_b1f[tid];
    ((float*)(sm + K1_B2))[tid] = b2g[tid];

    float acc[2][8][4];
    int pt0 = -1;

    int tile = blockIdx.x;
    if (tile < ntiles) {
        int t0 = tile * 64;
        #pragma unroll
        for (int i = 0; i < 8; ++i) {
            int idx = tid + i * 256;
            int r = idx >> 5, ch = idx & 31;
            if (t0 + r < T)
                cpa16(sb + K1_BUF0 + (u32)idx * 16,
                      (const char*)(x + (size_t)(t0 + r) * 128) + ch * 16);
        }
    }
    CP_COMMIT();

    #pragma unroll 1
    for (; tile < ntiles; tile += gridDim.x) {
        const int t0 = tile * 64;

        CP_WAIT0();
        __syncthreads();

        #pragma unroll
        for (int i = 0; i < 8; ++i) {
            int idx = tid + i * 256;
            int r = idx >> 5, c = (idx & 31) * 4;
            float4 v = *reinterpret_cast<const float4*>(sm + K1_BUF0 + (u32)idx * 16);
            u32 h01 = pack2h(__float2half_rn(v.x), __float2half_rn(v.y));
            u32 h23 = pack2h(__float2half_rn(v.z), __float2half_rn(v.w));
            u32 o = (u32)r * 256 + (((u32)c * 2) ^ (((u32)(r & 7)) << 4));
            sts64(sb + K1_XAH + o, h01, h23);
        }
        __syncthreads();

        #pragma unroll
        for (int i = 0; i < 16; ++i) {
            int idx = tid + i * 256;
            int n = idx >> 4, seg = idx & 15;
            u32 o = (u32)n * 256 + (u32)seg * 16;
            cpa16(sb + K1_W1H + (o ^ (((u32)(n & 7)) << 4)), (const char*)g_w1h + o);
        }
        CP_COMMIT();

        if (pt0 >= 0) {
            const float* b2s = (const float*)(sm + K1_B2);
            #pragma unroll
            for (int mt = 0; mt < 2; ++mt) {
                int tA = pt0 + wm + mt * 16 + g;
                int tB = tA + 8;
                float* rowA = nullptr; float* rowB = nullptr;
                if (tA < T) {
                    int nd = (cofs == 0) ? tok[tA] : tok[T + tA];
                    rowA = g_nf + (size_t)nd * 128;
                }
                if (tB < T) {
                    int nd = (cofs == 0) ? tok[tB] : tok[T + tB];
                    rowB = g_nf + (size_t)nd * 128;
                }
                #pragma unroll
                for (int nt = 0; nt < 8; ++nt) {
                    int c0 = wn + nt * 8 + q * 2;
                    float bx = b2s[c0], by = b2s[c0 + 1];
                    float a0 = acc[mt][nt][0] + bx;
                    float a1 = acc[mt][nt][1] + by;
                    float a2 = acc[mt][nt][2] + bx;
                    float a3 = acc[mt][nt][3] + by;
                    float p0 = __shfl_xor_sync(0xffffffffu, a0, 1);
                    float p1 = __shfl_xor_sync(0xffffffffu, a1, 1);
                    float p2 = __shfl_xor_sync(0xffffffffu, a2, 1);
                    float p3 = __shfl_xor_sync(0xffffffffu, a3, 1);
                    if (evenq) {
                        int cl = c0 - cofs;
                        if (rowA) red4(rowA + cl, a0, a1, p0, p1);
                        if (rowB) red4(rowB + cl, a2, a3, p2, p3);
                    }
                }
            }
        }
        pt0 = t0;

        CP_WAIT0();
        __syncthreads();

        // GEMM1
        #pragma unroll
        for (int mt = 0; mt < 2; ++mt)
            #pragma unroll
            for (int nt = 0; nt < 8; ++nt)
                #pragma unroll
                for (int j = 0; j < 4; ++j) acc[mt][nt][j] = 0.f;
        {
            const u32 PA = K1_XAH + (u32)(wm + lr8 + ((l >> 3) & 1) * 8) * 256u + keyX;
            const u32 PB = K1_W1H + (u32)(wn + lr8 + ((l >> 4) & 1) * 8) * 256u + keyX;
            #pragma unroll
            for (int kt = 0; kt < 8; ++kt) {
                u32 ca = (u32)kt * 32 + aCX, cb = (u32)kt * 32 + bCX;
                u32 Ah[2][4];
                ldsm4(sb + ((PA)         ^ ca), Ah[0][0], Ah[0][1], Ah[0][2], Ah[0][3]);
                ldsm4(sb + ((PA + 4096u) ^ ca), Ah[1][0], Ah[1][1], Ah[1][2], Ah[1][3]);
                #pragma unroll
                for (int ntg = 0; ntg < 4; ++ntg) {
                    u32 bh[4];
                    ldsm4(sb + ((PB + (u32)ntg * 4096u) ^ cb), bh[0], bh[1], bh[2], bh[3]);
                    #pragma unroll
                    for (int sub = 0; sub < 2; ++sub) {
                        int nt = ntg * 2 + sub;
                        #pragma unroll
                        for (int mt = 0; mt < 2; ++mt)
                            mma16816(acc[mt][nt], Ah[mt], bh[sub * 2], bh[sub * 2 + 1]);
                    }
                }
            }
        }
        __syncthreads();

        // W2 slab0 -> BUF0, slab1 -> BUF1 (W1H dead; epilogue covers latency)
        #pragma unroll
        for (int i = 0; i < 8; ++i) {
            int idx = tid + i * 256;
            int n = idx >> 3, seg = idx & 7;
            u32 o = (u32)n * 128 + (u32)seg * 16;
            u32 sw = o ^ (((u32)(n & 7)) << 4);
            cpa16(sb + K1_BUF0 + sw,
                  (const char*)g_w2h + (size_t)n * 512 + (size_t)seg * 16);
            cpa16(sb + K1_BUF1 + sw,
                  (const char*)g_w2h + (size_t)n * 512 + 128 + (size_t)seg * 16);
        }
        CP_COMMIT();

        // epilogue1
        {
            const float* b1s = (const float*)(sm + K1_B1);
            const u32 kr = (u32)g << 4;
            #pragma unroll
            for (int mt = 0; mt < 2; ++mt) {
                u32 row = (u32)(wm + mt * 16 + g);
                #pragma unroll
                for (int nt = 0; nt < 8; ++nt) {
                    int c0 = wn + nt * 8 + q * 2;
                    float bx = b1s[c0], by = b1s[c0 + 1];
                    float f0 = fmaxf(acc[mt][nt][0] + bx, 0.f);
                    float f1 = fmaxf(acc[mt][nt][1] + by, 0.f);
                    float f2 = fmaxf(acc[mt][nt][2] + bx, 0.f);
                    float f3 = fmaxf(acc[mt][nt][3] + by, 0.f);
                    u32 col = ((u32)c0 * 2) ^ kr;
                    sts32(sb + K1_A2H + row * 512 + col,
                          pack2h(__float2half_rn(f0), __float2half_rn(f1)));
                    sts32(sb + K1_A2H + (row + 8) * 512 + col,
                          pack2h(__float2half_rn(f2), __float2half_rn(f3)));
                }
            }
        }
        CP_WAIT0();
        __syncthreads();

        // GEMM2 (4 slabs of k=64)
        #pragma unroll
        for (int mt = 0; mt < 2; ++mt)
            #pragma unroll
            for (int nt = 0; nt < 8; ++nt)
                #pragma unroll
                for (int j = 0; j < 4; ++j) acc[mt][nt][j] = 0.f;
        {
            const u32 PA2 = K1_A2H + (u32)(wm + lr8 + ((l >> 3) & 1) * 8) * 512u + keyX;
            const u32 PW2 = ((u32)(wn + lr8 + ((l >> 4) & 1) * 8) * 128u) ^ keyX;
            #pragma unroll 1
            for (int s = 0; s < 4; ++s) {
                if (s == 1 || s == 2) {
                    u32 dB = (s == 1) ? K1_BUF0 : K1_BUF1;
                    #pragma unroll
                    for (int i = 0; i < 8; ++i) {
                        int idx = tid + i * 256;
                        int n = idx >> 3, seg = idx & 7;
                        u32 o = (u32)n * 128 + (u32)seg * 16;
                        size_t src = (size_t)n * 512 + (size_t)(s + 1) * 128 + (size_t)seg * 16;
                        cpa16(sb + dB + (o ^ (((u32)(n & 7)) << 4)), (const char*)g_w2h + src);
                    }
                    CP_COMMIT();
                } else if (s == 3) {
                    int tile2 = tile + gridDim.x;
                    if (tile2 < ntiles) {
                        int nt0 = tile2 * 64;
                        #pragma unroll
                        for (int i = 0; i < 8; ++i) {
                            int idx = tid + i * 256;
                            int r = idx >> 5, ch = idx & 31;
                            if (nt0 + r < T)
                                cpa16(sb + K1_BUF0 + (u32)idx * 16,
                                      (const char*)(x + (size_t)(nt0 + r) * 128) + ch * 16);
                        }
                    }
                    CP_COMMIT();
                }
                u32 bB = sb + ((s & 1) ? K1_BUF1 : K1_BUF0);
                #pragma unroll
                for (int ktL = 0; ktL < 4; ++ktL) {
                    int kt = s * 4 + ktL;
                    u32 ca = (u32)kt * 32 + aCX;
                    u32 cw = (u32)ktL * 32 + bCX;
                    u32 Ah[2][4];
                    ldsm4(sb + ((PA2)         ^ ca), Ah[0][0], Ah[0][1], Ah[0][2], Ah[0][3]);
                    ldsm4(sb + ((PA2 + 8192u) ^ ca), Ah[1][0], Ah[1][1], Ah[1][2], Ah[1][3]);
                    #pragma unroll
                    for (int ntg = 0; ntg < 4; ++ntg) {
                        u32 bh[4];
                        ldsm4(bB + ((PW2 + (u32)ntg * 2048u) ^ cw), bh[0], bh[1], bh[2], bh[3]);
                        #pragma unroll
                        for (int sub = 0; sub < 2; ++sub) {
                            int nt = ntg * 2 + sub;
                            #pragma unroll
                            for (int mt = 0; mt < 2; ++mt)
                                mma16816(acc[mt][nt], Ah[mt], bh[sub * 2], bh[sub * 2 + 1]);
                        }
                    }
                }
                if (s < 3) { CP_WAIT0(); }
                __syncthreads();
            }
        }
    }

    // final scatter
    if (pt0 >= 0) {
        const float* b2s = (const float*)(sm + K1_B2);
        #pragma unroll
        for (int mt = 0; mt < 2; ++mt) {
            int tA = pt0 + wm + mt * 16 + g;
            int tB = tA + 8;
            float* rowA = nullptr; float* rowB = nullptr;
            if (tA < T) {
                int nd = (cofs == 0) ? tok[tA] : tok[T + tA];
                rowA = g_nf + (size_t)nd * 128;
            }
            if (tB < T) {
                int nd = (cofs == 0) ? tok[tB] : tok[T + tB];
                rowB = g_nf + (size_t)nd * 128;
            }
            #pragma unroll
            for (int nt = 0; nt < 8; ++nt) {
                int c0 = wn + nt * 8 + q * 2;
                float bx = b2s[c0], by = b2s[c0 + 1];
                float a0 = acc[mt][nt][0] + bx;
                float a1 = acc[mt][nt][1] + by;
                float a2 = acc[mt][nt][2] + bx;
                float a3 = acc[mt][nt][3] + by;
                float p0 = __shfl_xor_sync(0xffffffffu, a0, 1);
                float p1 = __shfl_xor_sync(0xffffffffu, a1, 1);
                float p2 = __shfl_xor_sync(0xffffffffu, a2, 1);
                float p3 = __shfl_xor_sync(0xffffffffu, a3, 1);
                if (evenq) {
                    int cl = c0 - cofs;
                    if (rowA) red4(rowA + cl, a0, a1, p0, p1);
                    if (rowB) red4(rowB + cl, a2, a3, p2, p3);
                }
            }
        }
    }
}

// ---------------------------------------------------------------------------
// Kernel 2: PERSISTENT MLP2. 64 nodes/tile, 256 threads, 2 CTAs/SM, warp tile
// 32x32. Weights RESIDENT (loaded once); next nf tile staged during compute;
// biases in registers. XAH 0(16K, aliased A2) W1 16K(32K) W2 48K(32K)
// NFB 80K(32K fp32 staging). Total 112K.
// ---------------------------------------------------------------------------
#define M2_XAH  0u
#define M2_W1   16384u
#define M2_W2   49152u
#define M2_NFB  81920u
#define M2_SMEM 114688u

__global__ void __launch_bounds__(256, 2) k_mlp2(
    const float* __restrict__ b2g, float* __restrict__ out, int NN, int ntiles)
{
    extern __shared__ char sm[];
    const u32 sb = s2u(sm);
    const int tid = threadIdx.x, wid = tid >> 5, l = tid & 31;
    const int lr8 = l & 7;
    const int g = l >> 2, q = l & 3;
    const int wm = (wid & 1) * 32, wn = (wid >> 1) * 32;
    const u32 keyX = (u32)lr8 << 4;
    const u32 aCX = (u32)((l >> 4) & 1) * 16;
    const u32 bCX = (u32)((l >> 3) & 1) * 16;

    // biases -> registers
    float b1r[4][2], b2r[4][2];
    #pragma unroll
    for (int nt = 0; nt < 4; ++nt) {
        int c0 = wn + nt * 8 + q * 2;
        b1r[nt][0] = g_nb1f[c0]; b1r[nt][1] = g_nb1f[c0 + 1];
        b2r[nt][0] = b2g[c0];    b2r[nt][1] = b2g[c0 + 1];
    }

    // stage first nf tile
    int tile = blockIdx.x;
    if (tile < ntiles) {
        int n0 = tile * 64;
        #pragma unroll
        for (int i = 0; i < 8; ++i) {
            int idx = tid + i * 256;                  // 16B chunk 0..2047
            int r = idx >> 5, ch = idx & 31;
            if (n0 + r < NN)
                cpa16(sb + M2_NFB + (u32)idx * 16,
                      (const char*)(g_nf + (size_t)(n0 + r) * 128) + ch * 16);
        }
    }
    // resident weights: W1' and W2' (32K each)
    #pragma unroll
    for (int i = 0; i < 8; ++i) {
        int idx = tid + i * 256;                      // 0..2047
        int n = idx >> 4, seg = idx & 15;
        u32 o = (u32)n * 256 + (u32)seg * 16;
        u32 sw = o ^ (((u32)(n & 7)) << 4);
        cpa16(sb + M2_W1 + sw, (const char*)g_nw1h + o);
        cpa16(sb + M2_W2 + sw, (const char*)g_nw2h + o);
    }
    CP_COMMIT();

    const u32 PA = M2_XAH + (u32)(wm + lr8 + ((l >> 3) & 1) * 8) * 256u + keyX;
    const u32 PB1 = M2_W1 + (u32)(wn + lr8 + ((l >> 4) & 1) * 8) * 256u + keyX;
    const u32 PB2 = M2_W2 + (u32)(wn + lr8 + ((l >> 4) & 1) * 8) * 256u + keyX;

    #pragma unroll 1
    for (; tile < ntiles; tile += gridDim.x) {
        const int n0 = tile * 64;

        CP_WAIT0();
        __syncthreads();                              // nf staged (+ weights on iter 0)
                                                      // also fences prev-iter A2 reads
        // convert NFB -> XAH (fp16)
        #pragma unroll
        for (int i = 0; i < 8; ++i) {
            int idx = tid + i * 256;
            int r = idx >> 5, c = (idx & 31) * 4;
            float4 v = *reinterpret_cast<const float4*>(sm + M2_NFB + (u32)idx * 16);
            u32 h01 = pack2h(__float2half_rn(v.x), __float2half_rn(v.y));
            u32 h23 = pack2h(__float2half_rn(v.z), __float2half_rn(v.w));
            u32 o = (u32)r * 256 + (((u32)c * 2) ^ (((u32)(r & 7)) << 4));
            sts64(sb + M2_XAH + o, h01, h23);
        }
        __syncthreads();                              // XAH ready; NFB free

        // stage NEXT nf tile (hidden under both GEMMs)
        {
            int tile2 = tile + gridDim.x;
            if (tile2 < ntiles) {
                int m0 = tile2 * 64;
                #pragma unroll
                for (int i = 0; i < 8; ++i) {
                    int idx = tid + i * 256;
                    int r = idx >> 5, ch = idx & 31;
                    if (m0 + r < NN)
                        cpa16(sb + M2_NFB + (u32)idx * 16,
                              (const char*)(g_nf + (size_t)(m0 + r) * 128) + ch * 16);
                }
            }
            CP_COMMIT();
        }

        float acc[2][4][4];
        // ---- GEMM1 ----
        #pragma unroll
        for (int mt = 0; mt < 2; ++mt)
            #pragma unroll
            for (int nt = 0; nt < 4; ++nt)
                #pragma unroll
                for (int j = 0; j < 4; ++j) acc[mt][nt][j] = 0.f;
        #pragma unroll
        for (int kt = 0; kt < 8; ++kt) {
            u32 ca = (u32)kt * 32 + aCX, cb = (u32)kt * 32 + bCX;
            u32 Ah[2][4];
            ldsm4(sb + ((PA)         ^ ca), Ah[0][0], Ah[0][1], Ah[0][2], Ah[0][3]);
            ldsm4(sb + ((PA + 4096u) ^ ca), Ah[1][0], Ah[1][1], Ah[1][2], Ah[1][3]);
            #pragma unroll
            for (int ntg = 0; ntg < 2; ++ntg) {
                u32 bh[4];
                ldsm4(sb + ((PB1 + (u32)ntg * 4096u) ^ cb), bh[0], bh[1], bh[2], bh[3]);
                #pragma unroll
                for (int sub = 0; sub < 2; ++sub) {
                    int nt = ntg * 2 + sub;
                    #pragma unroll
                    for (int mt = 0; mt < 2; ++mt)
                        mma16816(acc[mt][nt], Ah[mt], bh[sub * 2], bh[sub * 2 + 1]);
                }
            }
        }
        __syncthreads();                              // XAH reads done

        // epilogue1 -> A2 over XAH (bias from regs)
        {
            const u32 kr = (u32)g << 4;
            #pragma unroll
            for (int mt = 0; mt < 2; ++mt) {
                u32 row = (u32)(wm + mt * 16 + g);
                #pragma unroll
                for (int nt = 0; nt < 4; ++nt) {
                    int c0 = wn + nt * 8 + q * 2;
                    float f0 = fmaxf(acc[mt][nt][0] + b1r[nt][0], 0.f);
                    float f1 = fmaxf(acc[mt][nt][1] + b1r[nt][1], 0.f);
                    float f2 = fmaxf(acc[mt][nt][2] + b1r[nt][0], 0.f);
                    float f3 = fmaxf(acc[mt][nt][3] + b1r[nt][1], 0.f);
                    u32 col = ((u32)c0 * 2) ^ kr;
                    sts32(sb + M2_XAH + row * 256 + col,
                          pack2h(__float2half_rn(f0), __float2half_rn(f1)));
                    sts32(sb + M2_XAH + (row + 8) * 256 + col,
                          pack2h(__float2half_rn(f2), __float2half_rn(f3)));
                }
            }
        }
        __syncthreads();                              // A2 ready

        // ---- GEMM2 ----
        #pragma unroll
        for (int mt = 0; mt < 2; ++mt)
            #pragma unroll
            for (int nt = 0; nt < 4; ++nt)
                #pragma unroll
                for (int j = 0; j < 4; ++j) acc[mt][nt][j] = 0.f;
        #pragma unroll
        for (int kt = 0; kt < 8; ++kt) {
            u32 ca = (u32)kt * 32 + aCX, cb = (u32)kt * 32 + bCX;
            u32 Ah[2][4];
            ldsm4(sb + ((PA)         ^ ca), Ah[0][0], Ah[0][1], Ah[0][2], Ah[0][3]);
            ldsm4(sb + ((PA + 4096u) ^ ca), Ah[1][0], Ah[1][1], Ah[1][2], Ah[1][3]);
            #pragma unroll
            for (int ntg = 0; ntg < 2; ++ntg) {
                u32 bh[4];
                ldsm4(sb + ((PB2 + (u32)ntg * 4096u) ^ cb), bh[0], bh[1], bh[2], bh[3]);
                #pragma unroll
                for (int sub = 0; sub < 2; ++sub) {
                    int nt = ntg * 2 + sub;
                    #pragma unroll
                    for (int mt = 0; mt < 2; ++mt)
                        mma16816(acc[mt][nt], Ah[mt], bh[sub * 2], bh[sub * 2 + 1]);
                }
            }
        }

        // output (bias from regs); A2-read fence is next loop-top sync
        #pragma unroll
        for (int mt = 0; mt < 2; ++mt) {
            int rA = n0 + wm + mt * 16 + g;
            int rB = rA + 8;
            #pragma unroll
            for (int nt = 0; nt < 4; ++nt) {
                int c0 = wn + nt * 8 + q * 2;
                if (rA < NN)
                    *reinterpret_cast<float2*>(out + (size_t)rA * 128 + c0) =
                        make_float2(acc[mt][nt][0] + b2r[nt][0], acc[mt][nt][1] + b2r[nt][1]);
                if (rB < NN)
                    *reinterpret_cast<float2*>(out + (size_t)rB * 128 + c0) =
                        make_float2(acc[mt][nt][2] + b2r[nt][0], acc[mt][nt][3] + b2r[nt][1]);
            }
        }
    }
}

// ---------------------------------------------------------------------------
extern "C" void kernel_launch(void* const* d_in, const int* in_sizes, int n_in,
                              void* d_out, int out_size) {
    const float* x    = (const float*)d_in[0];
    const int*   tok  = (const int*)d_in[3];   // int32 (JAX x64 disabled)
    const float* op_g  = (const float*)d_in[4];
    const float* op_b  = (const float*)d_in[5];
    const float* op_m  = (const float*)d_in[6];
    const float* op_v  = (const float*)d_in[7];
    const float* op_w1 = (const float*)d_in[8];
    const float* op_b1 = (const float*)d_in[9];
    const float* op_w2 = (const float*)d_in[10];
    const float* op_b2 = (const float*)d_in[11];
    const float* nm_g  = (const float*)d_in[12];
    const float* nm_b  = (const float*)d_in[13];
    const float* nm_m  = (const float*)d_in[14];
    const float* nm_v  = (const float*)d_in[15];
    const float* nm_w1 = (const float*)d_in[16];
    const float* nm_b1 = (const float*)d_in[17];
    const float* nm_w2 = (const float*)d_in[18];
    const float* nm_b2 = (const float*)d_in[19];

    int T  = in_sizes[0] / 128;
    int NN = in_sizes[2];
    float* out = (float*)d_out;

    cudaFuncSetAttribute(k_mlp1, cudaFuncAttributeMaxDynamicSharedMemorySize, K1_SMEM);
    cudaFuncSetAttribute(k_mlp2, cudaFuncAttributeMaxDynamicSharedMemorySize, M2_SMEM);

    int nsm = 148;
    cudaDeviceGetAttribute(&nsm, cudaDevAttrMultiProcessorCount, 0);

    int n4 = (NN * 128) / 4;
    k_prep<<<2608, 256>>>(op_w1, op_g, op_v, op_w2, nm_w1, nm_g, nm_v, nm_w2,
                          op_b1, op_b, op_m, nm_b1, nm_b, nm_m, n4);

    int ntiles = (T + 63) / 64;
    int grid1 = 2 * nsm;
    if (grid1 > ntiles) grid1 = ntiles;
    k_mlp1<<<grid1, 256, K1_SMEM>>>(x, tok, op_b2, T, ntiles);

    int ntiles2 = (NN + 63) / 64;
    int grid2 = 2 * nsm;
    if (grid2 > ntiles2) grid2 = ntiles2;
    k_mlp2<<<grid2, 256, M2_SMEM>>>(nm_b2, out, NN, ntiles2);
}